// round 9
// baseline (speedup 1.0000x reference)
#include <cuda_runtime.h>
#include <cuda_bf16.h>
#include <math.h>

#define B_    128
#define Q_    16
#define D_    1024
#define E_    300
#define K_    11
#define CTAS_PER_B 8
#define DOCS_PER_CTA (D_/CTAS_PER_B)   // 128
#define THREADS1 128
#define E4    (E_/4)                   // 75 float4
#define QSTRIDE 304                    // floats (76 f4)
#define Q4S   (QSTRIDE/4)
#define SSTRIDE 136                    // mod 32 == 8 -> conflict-free RBF access

// partials: [1024 CTAs][16 q][13] (11 kacc + 1 simacc + pad)
__device__ float g_part[B_*CTAS_PER_B*Q_*13];
__device__ int   g_count[B_];          // zero-init; reset by last CTA each run

__global__ __launch_bounds__(THREADS1, 4)
void knrm_part_kernel(const int* __restrict__ doctoks,
                      const int* __restrict__ querytoks,
                      const float* __restrict__ emb,
                      const float* __restrict__ mus,
                      const float* __restrict__ sigmas,
                      const float* __restrict__ fc_w,
                      const float* __restrict__ fc_b,
                      float* __restrict__ out)
{
    __shared__ float qn[Q_*QSTRIDE];       // 16 x 304
    __shared__ float s_sh[Q_*SSTRIDE];     // 16 x 136
    __shared__ float tmp16[16];
    __shared__ int last_flag;

    const int tid  = threadIdx.x;
    const int b    = blockIdx.x >> 3;
    const int cta  = blockIdx.x & 7;
    const int wid  = tid >> 5;
    const int lane = tid & 31;
    const int p    = lane & 1;             // e-parity: reads f4 indices 2j+p
    const int slot0 = wid*16 + (lane >> 1);// doc slot (shared with partner lane)

    // ---- load + normalize query embeddings into shared ----
    for (int i = tid; i < Q_*E_; i += THREADS1) {
        int q = i / E_, e = i - q*E_;
        int t = querytoks[b*Q_ + q];
        qn[q*QSTRIDE + e] = emb[t*E_ + e];
    }
    __syncthreads();
    {
        int q = tid >> 3, l = tid & 7;     // 16 q-rows x 8 lanes
        float ss = 0.f;
        for (int e = l; e < E_; e += 8) { float v = qn[q*QSTRIDE + e]; ss += v*v; }
        #pragma unroll
        for (int o = 4; o > 0; o >>= 1) ss += __shfl_down_sync(0xffffffffu, ss, o, 8);
        if (l == 0) tmp16[q] = 1.0f / (sqrtf(ss) + 1e-9f);
    }
    __syncthreads();
    for (int i = tid; i < Q_*E_; i += THREADS1) {
        int q = i / E_, e = i - q*E_;
        qn[q*QSTRIDE + e] *= tmp16[q];
    }
    __syncthreads();

    // ---- dot products: lane-pair shares 2 docs; parity-interleaved E ----
    const int t0 = doctoks[b*D_ + cta*DOCS_PER_CTA + slot0];
    const int t1 = doctoks[b*D_ + cta*DOCS_PER_CTA + slot0 + 64];
    const float4* p0 = reinterpret_cast<const float4*>(emb) + (long)t0 * E4;
    const float4* p1 = reinterpret_cast<const float4*>(emb) + (long)t1 * E4;
    const float4* qn4 = reinterpret_cast<const float4*>(qn);
    const float4 zero4 = make_float4(0.f, 0.f, 0.f, 0.f);

    float acc0[Q_], acc1[Q_];
    #pragma unroll
    for (int q = 0; q < Q_; q++) { acc0[q] = 0.f; acc1[q] = 0.f; }
    float dd0 = 0.f, dd1 = 0.f;

    auto fmastep = [&](const float4 a, const float4 c, int idx) {
        dd0 = fmaf(a.x,a.x, fmaf(a.y,a.y, fmaf(a.z,a.z, fmaf(a.w,a.w, dd0))));
        dd1 = fmaf(c.x,c.x, fmaf(c.y,c.y, fmaf(c.z,c.z, fmaf(c.w,c.w, dd1))));
        #pragma unroll
        for (int q = 0; q < Q_; q++) {
            float4 v = qn4[q*Q4S + idx];
            acc0[q] = fmaf(a.x,v.x, fmaf(a.y,v.y, fmaf(a.z,v.z, fmaf(a.w,v.w, acc0[q]))));
            acc1[q] = fmaf(c.x,v.x, fmaf(c.y,v.y, fmaf(c.z,v.z, fmaf(c.w,v.w, acc1[q]))));
        }
    };

    // this lane consumes indices {2j+p : j=0..36} plus (p==0 ? 74 : nothing)
    float4 a0 = p0[p],     c0 = p1[p];
    float4 a1 = p0[2 + p], c1 = p1[2 + p];
    #pragma unroll 5
    for (int j = 0; j < 35; j++) {          // prefetch idx 2(j+2)+p <= 73, always valid
        float4 an = p0[2*(j+2) + p];
        float4 cn = p1[2*(j+2) + p];
        fmastep(a0, c0, 2*j + p);
        a0 = a1; c0 = c1; a1 = an; c1 = cn;
    }
    {   // j=35: prefetch the tail value (idx 74 for p==0, zero for p==1)
        float4 an = zero4, cn = zero4;
        if (p == 0) { an = p0[74]; cn = p1[74]; }
        fmastep(a0, c0, 70 + p);
        a0 = a1; c0 = c1; a1 = an; c1 = cn;
    }
    fmastep(a0, c0, 72 + p);                // j=36
    a0 = a1; c0 = c1;
    fmastep(a0, c0, 74);                    // tail: p==1 stream is zero4 -> no-op

    // ---- combine the two e-parities (lanes l and l^1), once ----
    #pragma unroll
    for (int q = 0; q < Q_; q++) {
        acc0[q] += __shfl_xor_sync(0xffffffffu, acc0[q], 1);
        acc1[q] += __shfl_xor_sync(0xffffffffu, acc1[q], 1);
    }
    dd0 += __shfl_xor_sync(0xffffffffu, dd0, 1);
    dd1 += __shfl_xor_sync(0xffffffffu, dd1, 1);

    if (p == 0) {
        const float inv0 = 1.0f / (sqrtf(dd0) + 1e-9f);
        const float inv1 = 1.0f / (sqrtf(dd1) + 1e-9f);
        #pragma unroll
        for (int q = 0; q < Q_; q++) {
            s_sh[q*SSTRIDE + slot0]      = acc0[q] * inv0;
            s_sh[q*SSTRIDE + slot0 + 64] = acc1[q] * inv1;
        }
    }
    __syncthreads();

    // ---- RBF bank: 8 threads per q, each covers 16 docs ----
    const int myq = tid >> 3, myl = tid & 7;
    float mu_r[K_], w_r[K_];
    #pragma unroll
    for (int k = 0; k < K_; k++) {
        mu_r[k] = mus[k];
        float sg = sigmas[k];
        w_r[k] = -0.5f/(sg*sg);
    }
    float kacc[K_];
    #pragma unroll
    for (int k = 0; k < K_; k++) kacc[k] = 0.f;
    float simacc = 0.f;

    #pragma unroll 4
    for (int j = myl; j < DOCS_PER_CTA; j += 8) {
        float s = s_sh[myq*SSTRIDE + j];
        simacc += s;
        #pragma unroll
        for (int k = 0; k < K_; k++) {
            float dif = s - mu_r[k];
            kacc[k] += __expf(w_r[k]*dif*dif);
        }
    }

    #pragma unroll
    for (int k = 0; k < K_; k++) {
        float v = kacc[k];
        #pragma unroll
        for (int o = 4; o > 0; o >>= 1) v += __shfl_down_sync(0xffffffffu, v, o, 8);
        kacc[k] = v;
    }
    {
        float v = simacc;
        #pragma unroll
        for (int o = 4; o > 0; o >>= 1) v += __shfl_down_sync(0xffffffffu, v, o, 8);
        simacc = v;
    }
    if (myl == 0) {
        float* dst = &g_part[(blockIdx.x*Q_ + myq)*13];
        #pragma unroll
        for (int k = 0; k < K_; k++) dst[k] = kacc[k];
        dst[11] = simacc;
    }

    // ---- fused finalization: last CTA of this batch reduces + scores ----
    __syncthreads();
    if (tid == 0) {
        __threadfence();                       // release our partials
        int old = atomicAdd(&g_count[b], 1);
        last_flag = (old == CTAS_PER_B - 1);
    }
    __syncthreads();
    if (!last_flag) return;

    if (tid < 32) {
        __threadfence();                       // acquire other CTAs' partials
        const int lane2 = tid;
        const int q = lane2 & 15;
        const bool active = (lane2 < 16);

        float kb[K_];
        #pragma unroll
        for (int k = 0; k < K_; k++) kb[k] = 0.f;
        float sim = 0.f;
        #pragma unroll
        for (int cc = 0; cc < CTAS_PER_B; cc++) {
            const float* src = &g_part[((b*CTAS_PER_B + cc)*Q_ + q)*13];
            #pragma unroll
            for (int k = 0; k < K_; k++) kb[k] += src[k];
            sim += src[11];
        }
        const bool m = (sim != 0.0f) && active;
        float score = fc_b[0];
        #pragma unroll
        for (int k = 0; k < K_; k++) {
            float v = m ? logf(kb[k] + 1e-6f) : 0.0f;
            #pragma unroll
            for (int o = 8; o > 0; o >>= 1) v += __shfl_down_sync(0xffffffffu, v, o, 16);
            score = fmaf(v, fc_w[k], score);
        }
        if (lane2 == 0) {
            out[b] = score;
            g_count[b] = 0;                    // reset for next run / replay
        }
    }
}

extern "C" void kernel_launch(void* const* d_in, const int* in_sizes, int n_in,
                              void* d_out, int out_size)
{
    const int*   doctoks   = (const int*)  d_in[0];
    const int*   querytoks = (const int*)  d_in[1];
    // d_in[2] = query_idf (unused)
    const float* emb       = (const float*)d_in[3];
    const float* mus       = (const float*)d_in[4];
    const float* sigmas    = (const float*)d_in[5];
    const float* fc_w      = (const float*)d_in[6];
    const float* fc_b      = (const float*)d_in[7];
    float* out = (float*)d_out;

    knrm_part_kernel<<<B_*CTAS_PER_B, THREADS1>>>(
        doctoks, querytoks, emb, mus, sigmas, fc_w, fc_b, out);
}